// round 5
// baseline (speedup 1.0000x reference)
#include <cuda_runtime.h>
#include <cstdint>

#define M_TOK 8192
#define D_DIM 2048
#define H_DIM 8192

// device-global scratch (no allocation allowed in kernel_launch)
__device__ float g_x2[(size_t)M_TOK * H_DIM];        // relu(y1)
__device__ float g_tp[8 * (size_t)M_TOK * 16];       // k-split partials of T = X @ lora_a
__device__ float g_ts[(size_t)M_TOK * 16];           // summed T

// ---------------------------------------------------------------------------
__device__ __forceinline__ uint32_t f2tf32(float x) {
    uint32_t u;
    asm("cvt.rna.tf32.f32 %0, %1;" : "=r"(u) : "f"(x));
    return u;
}
__device__ __forceinline__ void mma1688(float* d, uint32_t a0, uint32_t a1,
                                        uint32_t a2, uint32_t a3,
                                        uint32_t b0, uint32_t b1) {
    asm volatile("mma.sync.aligned.m16n8k8.row.col.f32.tf32.tf32.f32 "
                 "{%0,%1,%2,%3}, {%4,%5,%6,%7}, {%8,%9}, {%0,%1,%2,%3};"
                 : "+f"(d[0]), "+f"(d[1]), "+f"(d[2]), "+f"(d[3])
                 : "r"(a0), "r"(a1), "r"(a2), "r"(a3), "r"(b0), "r"(b1));
}

// ---------------------------------------------------------------------------
// LoRA stage 1: Tp[split][m][r] = sum_{k in split chunk} X[m,k] * A[k,r]
// ---------------------------------------------------------------------------
__global__ __launch_bounds__(256) void lora_t(const float* __restrict__ X,
                                              const float* __restrict__ A,
                                              float* __restrict__ Tp,
                                              int K, int KC)
{
    __shared__ float As[128][17];
    const int tid = threadIdx.x, lane = tid & 31, w = tid >> 5;
    const int m0 = blockIdx.x * 32 + w * 4;
    const int k0 = blockIdx.y * KC;

    float acc[4][16];
#pragma unroll
    for (int rr = 0; rr < 4; rr++)
#pragma unroll
        for (int r = 0; r < 16; r++) acc[rr][r] = 0.f;

    for (int kt = 0; kt < KC; kt += 128) {
        __syncthreads();
#pragma unroll
        for (int i = 0; i < 2; i++) {
            int c = tid + 256 * i;
            int row = c >> 2, q = (c & 3) * 4;
            float4 v = *(const float4*)(A + (size_t)(k0 + kt + row) * 16 + q);
            As[row][q] = v.x; As[row][q + 1] = v.y;
            As[row][q + 2] = v.z; As[row][q + 3] = v.w;
        }
        __syncthreads();
#pragma unroll
        for (int j = 0; j < 4; j++) {
            const int kl = lane + 32 * j;
            float x[4];
#pragma unroll
            for (int rr = 0; rr < 4; rr++)
                x[rr] = X[(size_t)(m0 + rr) * K + k0 + kt + kl];
#pragma unroll
            for (int r = 0; r < 16; r++) {
                const float a = As[kl][r];
#pragma unroll
                for (int rr = 0; rr < 4; rr++)
                    acc[rr][r] = fmaf(x[rr], a, acc[rr][r]);
            }
        }
    }

    float keep[4];
#pragma unroll
    for (int r = 0; r < 16; r++) {
#pragma unroll
        for (int rr = 0; rr < 4; rr++) {
            float v = acc[rr][r];
#pragma unroll
            for (int s = 16; s; s >>= 1) v += __shfl_xor_sync(~0u, v, s);
            if (lane == r) keep[rr] = v;
        }
    }
    if (lane < 16) {
        float* o = Tp + (size_t)blockIdx.y * (M_TOK * 16);
#pragma unroll
        for (int rr = 0; rr < 4; rr++)
            o[(size_t)(m0 + rr) * 16 + lane] = keep[rr];
    }
}

__global__ __launch_bounds__(256) void lora_sum(const float* __restrict__ Tp,
                                                float* __restrict__ Ts, int split)
{
    const int i = blockIdx.x * 256 + threadIdx.x;
    const float4* p = (const float4*)Tp;
    float4 a = p[i];
    for (int s = 1; s < split; s++) {
        float4 b = p[i + (size_t)s * 32768];
        a.x += b.x; a.y += b.y; a.z += b.z; a.w += b.w;
    }
    ((float4*)Ts)[i] = a;
}

// ---------------------------------------------------------------------------
// tf32 mma.sync GEMM: Y = X @ dq(Wq)^T + bias + Ts@LB [relu]
// CTA 128x128, BK=16, 256 thr, 4-stage smem ring, double-reg-buffered B path.
// ---------------------------------------------------------------------------
template<bool RELU, int KTILES, int NT, int GROUP>
__global__ __launch_bounds__(256, 2) void gemm_mma(
    const float* __restrict__ X, const int* __restrict__ Wq,
    const float* __restrict__ Wsc, const float* __restrict__ bias,
    const float* __restrict__ Ts, const float* __restrict__ LB,
    float* __restrict__ Y)
{
    constexpr int K   = KTILES * 16;
    constexpr int KB  = K / 64;
    constexpr int NTILES = NT / 128;
    constexpr int TOT = KTILES + 1;
    constexpr int ASZ = 128 * 16 * 4;
    constexpr int BSZ = 128 * 16 * 4;
    constexpr int STG = ASZ + BSZ;      // 16 KB
    constexpr int NST = 4;

    extern __shared__ __align__(16) char smem[];
    float* sbias = (float*)(smem + NST * STG);

    const int tid  = threadIdx.x;
    const int lane = tid & 31;
    const int wid  = tid >> 5;
    const int wm = wid & 3, wn = wid >> 2;
    const int lr = lane >> 2, lc = lane & 3;
    const uint32_t xoff = (uint32_t)((lc ^ (lr & 3)) << 4);

    constexpr int NPG = GROUP * NTILES;
    const int pid = blockIdx.x;
    const int grp = pid / NPG, rem = pid % NPG;
    const int bm0 = (grp * GROUP + rem % GROUP) * 128;
    const int bn0 = (rem / GROUP) * 128;

    if (tid < 128) sbias[tid] = bias[bn0 + tid];

    const int r  = tid >> 2;
    const int j4 = tid & 3;

    float4 ra[2];                 // A staging (single set)
    uint4  rbB[2][2];             // B staging (double set)
    float  sB[2][2];

    auto LOADB = [&](int it, int set) {
        if (it >= TOT) return;
        if (it < KTILES) {
            const int k0 = it * 16;
#pragma unroll
            for (int j = 0; j < 2; j++) {
                const int row = r + 64 * j;
                rbB[set][j] = *(const uint4*)(Wq + (size_t)(bn0 + row) * K + k0 + j4 * 4);
                sB[set][j]  = Wsc[(size_t)(bn0 + row) * KB + (it >> 2)];
            }
        } else {
#pragma unroll
            for (int j = 0; j < 2; j++) {
                const int row = r + 64 * j;
                float b[4];
#pragma unroll
                for (int e = 0; e < 4; e++)
                    b[e] = LB[(size_t)(j4 * 4 + e) * NT + bn0 + row];
                rbB[set][j] = make_uint4(__float_as_uint(b[0]), __float_as_uint(b[1]),
                                         __float_as_uint(b[2]), __float_as_uint(b[3]));
            }
        }
    };
    auto LOADA = [&](int it) {
        if (it >= TOT) return;
        if (it < KTILES) {
            const int k0 = it * 16;
#pragma unroll
            for (int j = 0; j < 2; j++)
                ra[j] = *(const float4*)(X + (size_t)(bm0 + r + 64 * j) * K + k0 + j4 * 4);
        } else {
#pragma unroll
            for (int j = 0; j < 2; j++)
                ra[j] = *(const float4*)(Ts + (size_t)(bm0 + r + 64 * j) * 16 + j4 * 4);
        }
    };
    auto STS = [&](int it, int set) {
        char* sA = smem + (it & (NST - 1)) * STG;
        char* sB_ = sA + ASZ;
        const bool mn = (it < KTILES);
#pragma unroll
        for (int j = 0; j < 2; j++) {
            const int row = r + 64 * j;
            const float av[4] = {ra[j].x, ra[j].y, ra[j].z, ra[j].w};
            const uint32_t qv[4] = {rbB[set][j].x, rbB[set][j].y,
                                    rbB[set][j].z, rbB[set][j].w};
            const float sc = sB[set][j];
#pragma unroll
            for (int e = 0; e < 4; e++) {
                const uint32_t sw = (uint32_t)(((e ^ (row & 3)) << 2) + j4) * 4;
                *(uint32_t*)(sA  + (uint32_t)row * 64 + sw) = f2tf32(av[e]);
                float v = mn ? ((float)(int)qv[e] - 7.5f) * sc
                             : __uint_as_float(qv[e]);
                *(uint32_t*)(sB_ + (uint32_t)row * 64 + sw) = f2tf32(v);
            }
        }
    };

    float acc[2][8][4];
#pragma unroll
    for (int i = 0; i < 2; i++)
#pragma unroll
        for (int j = 0; j < 8; j++)
#pragma unroll
            for (int k = 0; k < 4; k++) acc[i][j][k] = 0.f;

    // prologue: tile0 -> stage0; tile1 staged in regs (B set1)
    LOADB(0, 0); LOADA(0);
    STS(0, 0);
    LOADB(1, 1); LOADA(1);
    __syncthreads();

    for (int it = 0; it < TOT; ++it) {
        LOADB(it + 2, it & 1);          // early: 2-phase LDG->STS distance for Wq

        // ---- compute stage it&3 ----
        {
            const char* sA = smem + (it & (NST - 1)) * STG;
            const char* sB_ = sA + ASZ;
            uint32_t a[2][2][4];
#pragma unroll
            for (int mt = 0; mt < 2; mt++) {
                const uint32_t row = (uint32_t)(32 * wm + 16 * mt + lr);
                *(uint4*)a[mt][0] = *(const uint4*)(sA + row * 64 + xoff);
                *(uint4*)a[mt][1] = *(const uint4*)(sA + (row + 8) * 64 + xoff);
            }
#pragma unroll
            for (int nt = 0; nt < 8; nt++) {
                const uint32_t n = (uint32_t)(64 * wn + 8 * nt + lr);
                uint32_t b[4];
                *(uint4*)b = *(const uint4*)(sB_ + n * 64 + xoff);
#pragma unroll
                for (int mt = 0; mt < 2; mt++) {
                    mma1688(acc[mt][nt], a[mt][0][0], a[mt][1][0],
                            a[mt][0][1], a[mt][1][1], b[0], b[1]);
                    mma1688(acc[mt][nt], a[mt][0][2], a[mt][1][2],
                            a[mt][0][3], a[mt][1][3], b[2], b[3]);
                }
            }
        }

        if (it + 1 < TOT) STS(it + 1, (it + 1) & 1);
        LOADA(it + 2);                  // X: usually L2-hit; 1-phase distance ok
        __syncthreads();
    }

    // epilogue: bias (+relu)
#pragma unroll
    for (int mt = 0; mt < 2; mt++) {
        const int m = bm0 + 32 * wm + 16 * mt + lr;
#pragma unroll
        for (int nt = 0; nt < 8; nt++) {
            const int ncol = 64 * wn + 8 * nt + 2 * lc;
            const float b0 = sbias[ncol], b1 = sbias[ncol + 1];
            float v0 = acc[mt][nt][0] + b0, v1 = acc[mt][nt][1] + b1;
            float v2 = acc[mt][nt][2] + b0, v3 = acc[mt][nt][3] + b1;
            if (RELU) {
                v0 = fmaxf(v0, 0.f); v1 = fmaxf(v1, 0.f);
                v2 = fmaxf(v2, 0.f); v3 = fmaxf(v3, 0.f);
            }
            *(float2*)(Y + (size_t)m * NT + bn0 + ncol)       = make_float2(v0, v1);
            *(float2*)(Y + (size_t)(m + 8) * NT + bn0 + ncol) = make_float2(v2, v3);
        }
    }
}

// ---------------------------------------------------------------------------
extern "C" void kernel_launch(void* const* d_in, const int* in_sizes, int n_in,
                              void* d_out, int out_size)
{
    const float* x1      = (const float*)d_in[0];
    const int*   w_up_q  = (const int*)  d_in[1];
    const float* w_up_sc = (const float*)d_in[2];
    const float* b_up    = (const float*)d_in[3];
    const float* w_up_la = (const float*)d_in[4];
    const float* w_up_lb = (const float*)d_in[5];
    const int*   w_dn_q  = (const int*)  d_in[6];
    const float* w_dn_sc = (const float*)d_in[7];
    const float* b_dn    = (const float*)d_in[8];
    const float* w_dn_la = (const float*)d_in[9];
    const float* w_dn_lb = (const float*)d_in[10];
    float*       out     = (float*)d_out;

    float *x2, *tp, *ts;
    cudaGetSymbolAddress((void**)&x2, g_x2);
    cudaGetSymbolAddress((void**)&tp, g_tp);
    cudaGetSymbolAddress((void**)&ts, g_ts);

    constexpr int SMEM = 4 * (128 * 16 * 4 + 128 * 16 * 4) + 512;
    cudaFuncSetAttribute(gemm_mma<true, 128, H_DIM, 16>,
                         cudaFuncAttributeMaxDynamicSharedMemorySize, SMEM);
    cudaFuncSetAttribute(gemm_mma<false, 512, D_DIM, 32>,
                         cudaFuncAttributeMaxDynamicSharedMemorySize, SMEM);

    lora_t<<<dim3(M_TOK / 32, 4), 256>>>(x1, w_up_la, tp, D_DIM, D_DIM / 4);
    lora_sum<<<128, 256>>>(tp, ts, 4);
    gemm_mma<true, 128, H_DIM, 16><<<(M_TOK / 128) * (H_DIM / 128), 256, SMEM>>>(
        x1, w_up_q, w_up_sc, b_up, ts, w_up_lb, x2);

    lora_t<<<dim3(M_TOK / 32, 8), 256>>>(x2, w_dn_la, tp, H_DIM, H_DIM / 8);
    lora_sum<<<128, 256>>>(tp, ts, 8);
    gemm_mma<false, 512, D_DIM, 32><<<(M_TOK / 128) * (D_DIM / 128), 256, SMEM>>>(
        x2, w_dn_q, w_dn_sc, b_dn, ts, w_dn_lb, out);
}

// round 6
// speedup vs baseline: 2.8060x; 2.8060x over previous
#include <cuda_runtime.h>
#include <cstdint>

#define M_TOK 8192
#define D_DIM 2048
#define H_DIM 8192

// device-global scratch
__device__ float g_x2 [(size_t)M_TOK * H_DIM];   // relu(y1), tf32-rounded
__device__ float g_x1t[(size_t)M_TOK * D_DIM];   // x1 tf32-rounded
__device__ float g_wt [(size_t)H_DIM * D_DIM];   // dequantized weights (reused both layers)
__device__ float g_lbt[(size_t)H_DIM * 16];      // LB transposed [N,16]
__device__ float g_tp [8 * (size_t)M_TOK * 16];
__device__ float g_ts [(size_t)M_TOK * 16];

// ---------------------------------------------------------------------------
__device__ __forceinline__ uint32_t f2tf32(float x) {
    uint32_t u;
    asm("cvt.rna.tf32.f32 %0, %1;" : "=r"(u) : "f"(x));
    return u;
}
__device__ __forceinline__ float tf32f(float x) { return __uint_as_float(f2tf32(x)); }

__device__ __forceinline__ void mma1688(float* d, uint32_t a0, uint32_t a1,
                                        uint32_t a2, uint32_t a3,
                                        uint32_t b0, uint32_t b1) {
    asm volatile("mma.sync.aligned.m16n8k8.row.col.f32.tf32.tf32.f32 "
                 "{%0,%1,%2,%3}, {%4,%5,%6,%7}, {%8,%9}, {%0,%1,%2,%3};"
                 : "+f"(d[0]), "+f"(d[1]), "+f"(d[2]), "+f"(d[3])
                 : "r"(a0), "r"(a1), "r"(a2), "r"(a3), "r"(b0), "r"(b1));
}
__device__ __forceinline__ void cp16(uint32_t dst, const void* src) {
    asm volatile("cp.async.cg.shared.global [%0], [%1], 16;"
                 :: "r"(dst), "l"(src));
}

// ---------------------------------------------------------------------------
// prepasses
// ---------------------------------------------------------------------------
__global__ __launch_bounds__(256) void cvt_x(const float* __restrict__ in,
                                             float* __restrict__ out)
{   // tf32-round, vectorized
    size_t i = (size_t)blockIdx.x * 256 + threadIdx.x;
    float4 v = ((const float4*)in)[i];
    ((float4*)out)[i] = make_float4(tf32f(v.x), tf32f(v.y), tf32f(v.z), tf32f(v.w));
}

__global__ __launch_bounds__(256) void dq_w(const int* __restrict__ Wq,
                                            const float* __restrict__ Wsc,
                                            float* __restrict__ Wt, int K)
{   // Wt[row,k] = tf32((Wq-7.5)*scale), 4 elems/thread
    size_t i = (size_t)blockIdx.x * 256 + threadIdx.x;  // float4 index
    const int K4 = K >> 2;
    int row = (int)(i / K4), k4 = (int)(i % K4);
    int4 q = ((const int4*)(Wq))[i];
    float s = Wsc[(size_t)row * (K >> 6) + (k4 >> 4)];
    ((float4*)Wt)[i] = make_float4(tf32f(((float)q.x - 7.5f) * s),
                                   tf32f(((float)q.y - 7.5f) * s),
                                   tf32f(((float)q.z - 7.5f) * s),
                                   tf32f(((float)q.w - 7.5f) * s));
}

__global__ __launch_bounds__(256) void tr_lb(const float* __restrict__ LB,
                                             float* __restrict__ LBT, int NT)
{   // LBT[n][r] = tf32(LB[r][n])
    int n = blockIdx.x * 256 + threadIdx.x;
    float v[16];
#pragma unroll
    for (int r = 0; r < 16; r++) v[r] = tf32f(LB[(size_t)r * NT + n]);
#pragma unroll
    for (int r = 0; r < 16; r += 4)
        *(float4*)(LBT + (size_t)n * 16 + r) = make_float4(v[r], v[r+1], v[r+2], v[r+3]);
}

// ---------------------------------------------------------------------------
// LoRA: Tp[split][m][r] = partial X@A ; then sum -> Ts (tf32-rounded)
// ---------------------------------------------------------------------------
__global__ __launch_bounds__(256) void lora_t(const float* __restrict__ X,
                                              const float* __restrict__ A,
                                              float* __restrict__ Tp,
                                              int K, int KC)
{
    __shared__ float As[128][17];
    const int tid = threadIdx.x, lane = tid & 31, w = tid >> 5;
    const int m0 = blockIdx.x * 32 + w * 4;
    const int k0 = blockIdx.y * KC;

    float acc[4][16];
#pragma unroll
    for (int rr = 0; rr < 4; rr++)
#pragma unroll
        for (int r = 0; r < 16; r++) acc[rr][r] = 0.f;

    for (int kt = 0; kt < KC; kt += 128) {
        __syncthreads();
#pragma unroll
        for (int i = 0; i < 2; i++) {
            int c = tid + 256 * i;
            int row = c >> 2, q = (c & 3) * 4;
            float4 v = *(const float4*)(A + (size_t)(k0 + kt + row) * 16 + q);
            As[row][q] = v.x; As[row][q+1] = v.y; As[row][q+2] = v.z; As[row][q+3] = v.w;
        }
        __syncthreads();
#pragma unroll
        for (int j = 0; j < 4; j++) {
            const int kl = lane + 32 * j;
            float x[4];
#pragma unroll
            for (int rr = 0; rr < 4; rr++)
                x[rr] = X[(size_t)(m0 + rr) * K + k0 + kt + kl];
#pragma unroll
            for (int r = 0; r < 16; r++) {
                const float a = As[kl][r];
#pragma unroll
                for (int rr = 0; rr < 4; rr++)
                    acc[rr][r] = fmaf(x[rr], a, acc[rr][r]);
            }
        }
    }
    float keep[4];
#pragma unroll
    for (int r = 0; r < 16; r++) {
#pragma unroll
        for (int rr = 0; rr < 4; rr++) {
            float v = acc[rr][r];
#pragma unroll
            for (int s = 16; s; s >>= 1) v += __shfl_xor_sync(~0u, v, s);
            if (lane == r) keep[rr] = v;
        }
    }
    if (lane < 16) {
        float* o = Tp + (size_t)blockIdx.y * (M_TOK * 16);
#pragma unroll
        for (int rr = 0; rr < 4; rr++)
            o[(size_t)(m0 + rr) * 16 + lane] = keep[rr];
    }
}

__global__ __launch_bounds__(256) void lora_sum(const float* __restrict__ Tp,
                                                float* __restrict__ Ts, int split)
{
    const int i = blockIdx.x * 256 + threadIdx.x;
    const float4* p = (const float4*)Tp;
    float4 a = p[i];
    for (int s = 1; s < split; s++) {
        float4 b = p[i + (size_t)s * 32768];
        a.x += b.x; a.y += b.y; a.z += b.z; a.w += b.w;
    }
    ((float4*)Ts)[i] = make_float4(tf32f(a.x), tf32f(a.y), tf32f(a.z), tf32f(a.w));
}

// ---------------------------------------------------------------------------
// cp.async multistage tf32 GEMM: Y = Xt @ Wt^T + bias + Ts@LBT^T [relu][round]
// CTA 128x128, BK=16, 256 thr, 5-stage ring, LoRA = uniform extra k-tile.
// ---------------------------------------------------------------------------
template<bool RELU, bool ROUND_OUT, int KTILES, int NT, int GROUP>
__global__ __launch_bounds__(256, 2) void gemm_cp(
    const float* __restrict__ Xt, const float* __restrict__ Wt,
    const float* __restrict__ bias,
    const float* __restrict__ Ts, const float* __restrict__ LBT,
    float* __restrict__ Y)
{
    constexpr int K   = KTILES * 16;
    constexpr int NTILES = NT / 128;
    constexpr int TOT = KTILES + 1;
    constexpr int ASZ = 128 * 16 * 4;   // 8 KB
    constexpr int STG = 2 * ASZ;        // 16 KB
    constexpr int NST = 5;

    extern __shared__ __align__(16) char smem[];
    float* sbias = (float*)(smem + NST * STG);
    uint32_t sbase;
    asm("{ .reg .u64 t; cvta.to.shared.u64 t, %1; cvt.u32.u64 %0, t; }"
        : "=r"(sbase) : "l"(smem));

    const int tid  = threadIdx.x;
    const int lane = tid & 31;
    const int wid  = tid >> 5;
    const int wm = wid & 3, wn = wid >> 2;
    const int lr = lane >> 2, lc = lane & 3;
    const uint32_t xoff = (uint32_t)((lc ^ (lr & 3)) << 4);

    constexpr int NPG = GROUP * NTILES;
    const int pid = blockIdx.x;
    const int grp = pid / NPG, rem = pid % NPG;
    const int bm0 = (grp * GROUP + rem % GROUP) * 128;
    const int bn0 = (rem / GROUP) * 128;

    if (tid < 128) sbias[tid] = bias[bn0 + tid];

    const int r  = tid >> 2;       // 0..63
    const int j4 = tid & 3;
    const uint32_t qsw = (uint32_t)((j4 ^ (r & 3)) << 4);   // (r+64)&3 == r&3

    auto FILL = [&](int it) {
        if (it < TOT) {
            const uint32_t st = sbase + (uint32_t)(it % NST) * STG;
            const bool mn = (it < KTILES);
            const int k0 = it * 16;
#pragma unroll
            for (int j = 0; j < 2; j++) {
                const int row = r + 64 * j;
                const float* ga = mn ? Xt + (size_t)(bm0 + row) * K + k0 + j4 * 4
                                     : Ts + (size_t)(bm0 + row) * 16 + j4 * 4;
                const float* gb = mn ? Wt + (size_t)(bn0 + row) * K + k0 + j4 * 4
                                     : LBT + (size_t)(bn0 + row) * 16 + j4 * 4;
                cp16(st + (uint32_t)row * 64 + qsw, ga);
                cp16(st + ASZ + (uint32_t)row * 64 + qsw, gb);
            }
        }
        asm volatile("cp.async.commit_group;" ::: "memory");
    };

    float acc[2][8][4];
#pragma unroll
    for (int i = 0; i < 2; i++)
#pragma unroll
        for (int j = 0; j < 8; j++)
#pragma unroll
            for (int k = 0; k < 4; k++) acc[i][j][k] = 0.f;

#pragma unroll
    for (int p = 0; p < NST - 1; ++p) FILL(p);

    for (int it = 0; it < TOT; ++it) {
        asm volatile("cp.async.wait_group %0;" :: "n"(NST - 2) : "memory");
        __syncthreads();

        const char* sA = smem + (it % NST) * STG;
        const char* sB = sA + ASZ;
        uint32_t a[2][2][4];
#pragma unroll
        for (int mt = 0; mt < 2; mt++) {
            const uint32_t row = (uint32_t)(32 * wm + 16 * mt + lr);
            *(uint4*)a[mt][0] = *(const uint4*)(sA + row * 64 + xoff);
            *(uint4*)a[mt][1] = *(const uint4*)(sA + (row + 8) * 64 + xoff);
        }
#pragma unroll
        for (int nt = 0; nt < 8; nt++) {
            const uint32_t n = (uint32_t)(64 * wn + 8 * nt + lr);
            uint32_t b[4];
            *(uint4*)b = *(const uint4*)(sB + n * 64 + xoff);
#pragma unroll
            for (int mt = 0; mt < 2; mt++) {
                mma1688(acc[mt][nt], a[mt][0][0], a[mt][1][0],
                        a[mt][0][1], a[mt][1][1], b[0], b[1]);
                mma1688(acc[mt][nt], a[mt][0][2], a[mt][1][2],
                        a[mt][0][3], a[mt][1][3], b[2], b[3]);
            }
        }
        FILL(it + NST - 1);
    }

    // epilogue: bias (+relu) (+tf32 round for x2)
#pragma unroll
    for (int mt = 0; mt < 2; mt++) {
        const int m = bm0 + 32 * wm + 16 * mt + lr;
#pragma unroll
        for (int nt = 0; nt < 8; nt++) {
            const int ncol = 64 * wn + 8 * nt + 2 * lc;
            const float b0 = sbias[ncol], b1 = sbias[ncol + 1];
            float v[4] = {acc[mt][nt][0] + b0, acc[mt][nt][1] + b1,
                          acc[mt][nt][2] + b0, acc[mt][nt][3] + b1};
            if (RELU) {
#pragma unroll
                for (int e = 0; e < 4; e++) v[e] = fmaxf(v[e], 0.f);
            }
            if (ROUND_OUT) {
#pragma unroll
                for (int e = 0; e < 4; e++) v[e] = tf32f(v[e]);
            }
            *(float2*)(Y + (size_t)m * NT + bn0 + ncol)       = make_float2(v[0], v[1]);
            *(float2*)(Y + (size_t)(m + 8) * NT + bn0 + ncol) = make_float2(v[2], v[3]);
        }
    }
}

// ---------------------------------------------------------------------------
extern "C" void kernel_launch(void* const* d_in, const int* in_sizes, int n_in,
                              void* d_out, int out_size)
{
    const float* x1      = (const float*)d_in[0];
    const int*   w_up_q  = (const int*)  d_in[1];
    const float* w_up_sc = (const float*)d_in[2];
    const float* b_up    = (const float*)d_in[3];
    const float* w_up_la = (const float*)d_in[4];
    const float* w_up_lb = (const float*)d_in[5];
    const int*   w_dn_q  = (const int*)  d_in[6];
    const float* w_dn_sc = (const float*)d_in[7];
    const float* b_dn    = (const float*)d_in[8];
    const float* w_dn_la = (const float*)d_in[9];
    const float* w_dn_lb = (const float*)d_in[10];
    float*       out     = (float*)d_out;

    float *x2, *x1t, *wt, *lbt, *tp, *ts;
    cudaGetSymbolAddress((void**)&x2,  g_x2);
    cudaGetSymbolAddress((void**)&x1t, g_x1t);
    cudaGetSymbolAddress((void**)&wt,  g_wt);
    cudaGetSymbolAddress((void**)&lbt, g_lbt);
    cudaGetSymbolAddress((void**)&tp,  g_tp);
    cudaGetSymbolAddress((void**)&ts,  g_ts);

    constexpr int SMEM = 5 * (2 * 128 * 16 * 4) + 512;   // 80 KB + bias
    cudaFuncSetAttribute(gemm_cp<true, true, 128, H_DIM, 16>,
                         cudaFuncAttributeMaxDynamicSharedMemorySize, SMEM);
    cudaFuncSetAttribute(gemm_cp<false, false, 512, D_DIM, 32>,
                         cudaFuncAttributeMaxDynamicSharedMemorySize, SMEM);

    // ---- layer 1 ----
    cvt_x<<<(M_TOK * D_DIM / 4) / 256, 256>>>(x1, x1t);
    dq_w<<<((size_t)H_DIM * D_DIM / 4) / 256, 256>>>(w_up_q, w_up_sc, wt, D_DIM);
    tr_lb<<<H_DIM / 256, 256>>>(w_up_lb, lbt, H_DIM);
    lora_t<<<dim3(M_TOK / 32, 4), 256>>>(x1, w_up_la, tp, D_DIM, D_DIM / 4);
    lora_sum<<<128, 256>>>(tp, ts, 4);
    gemm_cp<true, true, 128, H_DIM, 16><<<(M_TOK / 128) * (H_DIM / 128), 256, SMEM>>>(
        x1t, wt, b_up, ts, lbt, x2);

    // ---- layer 2 ----
    dq_w<<<((size_t)D_DIM * H_DIM / 4) / 256, 256>>>(w_dn_q, w_dn_sc, wt, H_DIM);
    tr_lb<<<D_DIM / 256, 256>>>(w_dn_lb, lbt, D_DIM);
    lora_t<<<dim3(M_TOK / 32, 8), 256>>>(x2, w_dn_la, tp, H_DIM, H_DIM / 8);
    lora_sum<<<128, 256>>>(tp, ts, 8);
    gemm_cp<false, false, 512, D_DIM, 32><<<(M_TOK / 128) * (D_DIM / 128), 256, SMEM>>>(
        x2, wt, b_dn, ts, lbt, out);
}

// round 7
// speedup vs baseline: 5.7907x; 2.0637x over previous
#include <cuda_runtime.h>
#include <cuda_fp16.h>
#include <cstdint>

#define M_TOK 8192
#define D_DIM 2048
#define H_DIM 8192

// device-global scratch
__device__ __half g_x1h[(size_t)M_TOK * D_DIM];   // x1 -> half
__device__ __half g_x2h[(size_t)M_TOK * H_DIM];   // relu(y1) in half
__device__ __half g_wh [(size_t)H_DIM * D_DIM];   // dequantized weights (reused)
__device__ __half g_lbt[(size_t)H_DIM * 32];      // LB^T padded [N,32]
__device__ __half g_tsh[(size_t)M_TOK * 32];      // T padded [M,32]
__device__ float  g_tp [8 * (size_t)M_TOK * 16];

// ---------------------------------------------------------------------------
__device__ __forceinline__ void ldm4(uint32_t* r, uint32_t addr) {
    asm volatile("ldmatrix.sync.aligned.m8n8.x4.shared.b16 {%0,%1,%2,%3}, [%4];"
                 : "=r"(r[0]), "=r"(r[1]), "=r"(r[2]), "=r"(r[3]) : "r"(addr));
}
__device__ __forceinline__ void mma16816(float* d, const uint32_t* a,
                                         uint32_t b0, uint32_t b1) {
    asm volatile("mma.sync.aligned.m16n8k16.row.col.f32.f16.f16.f32 "
                 "{%0,%1,%2,%3}, {%4,%5,%6,%7}, {%8,%9}, {%0,%1,%2,%3};"
                 : "+f"(d[0]), "+f"(d[1]), "+f"(d[2]), "+f"(d[3])
                 : "r"(a[0]), "r"(a[1]), "r"(a[2]), "r"(a[3]), "r"(b0), "r"(b1));
}
__device__ __forceinline__ void cp16(uint32_t dst, const void* src) {
    asm volatile("cp.async.cg.shared.global [%0], [%1], 16;" :: "r"(dst), "l"(src));
}

// ---------------------------------------------------------------------------
// prepasses
// ---------------------------------------------------------------------------
__global__ __launch_bounds__(256) void cvt_x(const float* __restrict__ in,
                                             __half* __restrict__ out)
{   // 8 floats -> 8 halves per thread
    size_t i = ((size_t)blockIdx.x * 256 + threadIdx.x) * 8;
    float4 a = *(const float4*)(in + i);
    float4 b = *(const float4*)(in + i + 4);
    __half2 h[4] = {__floats2half2_rn(a.x, a.y), __floats2half2_rn(a.z, a.w),
                    __floats2half2_rn(b.x, b.y), __floats2half2_rn(b.z, b.w)};
    *(uint4*)(out + i) = *(uint4*)h;
}

__global__ __launch_bounds__(256) void dq_w(const int* __restrict__ Wq,
                                            const float* __restrict__ Wsc,
                                            __half* __restrict__ Wh, int K)
{   // 8 codes -> 8 halves per thread; 8 consecutive k share one scale block
    size_t i8 = (size_t)blockIdx.x * 256 + threadIdx.x;   // 8-elem chunk idx
    const int K8 = K >> 3;
    int row = (int)(i8 / K8), k8 = (int)(i8 % K8);
    float s = Wsc[(size_t)row * (K >> 6) + (k8 >> 3)];
    int4 q0 = ((const int4*)Wq)[i8 * 2];
    int4 q1 = ((const int4*)Wq)[i8 * 2 + 1];
    __half2 h[4] = {
        __floats2half2_rn(((float)q0.x - 7.5f) * s, ((float)q0.y - 7.5f) * s),
        __floats2half2_rn(((float)q0.z - 7.5f) * s, ((float)q0.w - 7.5f) * s),
        __floats2half2_rn(((float)q1.x - 7.5f) * s, ((float)q1.y - 7.5f) * s),
        __floats2half2_rn(((float)q1.z - 7.5f) * s, ((float)q1.w - 7.5f) * s)};
    *(uint4*)(Wh + i8 * 8) = *(uint4*)h;
}

__global__ __launch_bounds__(256) void tr_lb(const float* __restrict__ LB,
                                             __half* __restrict__ LBT, int NT)
{   // LBT[n][r] = LB[r][n] for r<16, 0 for 16<=r<32
    int n = blockIdx.x * 256 + threadIdx.x;
    __half2 h[16];
#pragma unroll
    for (int r = 0; r < 8; r++)
        h[r] = __floats2half2_rn(LB[(size_t)(2 * r) * NT + n],
                                 LB[(size_t)(2 * r + 1) * NT + n]);
#pragma unroll
    for (int r = 8; r < 16; r++) h[r] = __floats2half2_rn(0.f, 0.f);
#pragma unroll
    for (int c = 0; c < 4; c++)
        *(uint4*)(LBT + (size_t)n * 32 + c * 8) = ((uint4*)h)[c];
}

// ---------------------------------------------------------------------------
// LoRA: Tp[split][m][r] partials from half X, then sum -> padded half Ts
// ---------------------------------------------------------------------------
__global__ __launch_bounds__(256) void lora_t(const __half* __restrict__ X,
                                              const float* __restrict__ A,
                                              float* __restrict__ Tp,
                                              int K, int KC)
{
    __shared__ float As[128][17];
    const int tid = threadIdx.x, lane = tid & 31, w = tid >> 5;
    const int m0 = blockIdx.x * 32 + w * 4;
    const int k0 = blockIdx.y * KC;

    float acc[4][16];
#pragma unroll
    for (int rr = 0; rr < 4; rr++)
#pragma unroll
        for (int r = 0; r < 16; r++) acc[rr][r] = 0.f;

    for (int kt = 0; kt < KC; kt += 128) {
        __syncthreads();
#pragma unroll
        for (int i = 0; i < 2; i++) {
            int c = tid + 256 * i;
            int row = c >> 2, q = (c & 3) * 4;
            float4 v = *(const float4*)(A + (size_t)(k0 + kt + row) * 16 + q);
            As[row][q] = v.x; As[row][q+1] = v.y; As[row][q+2] = v.z; As[row][q+3] = v.w;
        }
        __syncthreads();
#pragma unroll
        for (int j = 0; j < 4; j++) {
            const int kl = lane + 32 * j;
            float x[4];
#pragma unroll
            for (int rr = 0; rr < 4; rr++)
                x[rr] = __half2float(X[(size_t)(m0 + rr) * K + k0 + kt + kl]);
#pragma unroll
            for (int r = 0; r < 16; r++) {
                const float a = As[kl][r];
#pragma unroll
                for (int rr = 0; rr < 4; rr++)
                    acc[rr][r] = fmaf(x[rr], a, acc[rr][r]);
            }
        }
    }
    float keep[4];
#pragma unroll
    for (int r = 0; r < 16; r++) {
#pragma unroll
        for (int rr = 0; rr < 4; rr++) {
            float v = acc[rr][r];
#pragma unroll
            for (int s = 16; s; s >>= 1) v += __shfl_xor_sync(~0u, v, s);
            if (lane == r) keep[rr] = v;
        }
    }
    if (lane < 16) {
        float* o = Tp + (size_t)blockIdx.y * (M_TOK * 16);
#pragma unroll
        for (int rr = 0; rr < 4; rr++)
            o[(size_t)(m0 + rr) * 16 + lane] = keep[rr];
    }
}

__global__ __launch_bounds__(256) void lora_sum(const float* __restrict__ Tp,
                                                __half* __restrict__ Ts, int split)
{   // thread handles (m, rq): 4 values -> half; also zero-pads cols 16-31
    const int i = blockIdx.x * 256 + threadIdx.x;   // < 32768
    const int m = i >> 2, rq = i & 3;
    const float4* p = (const float4*)Tp;
    float4 a = p[i];
    for (int s = 1; s < split; s++) {
        float4 b = p[i + (size_t)s * 32768];
        a.x += b.x; a.y += b.y; a.z += b.z; a.w += b.w;
    }
    __half2 h[2] = {__floats2half2_rn(a.x, a.y), __floats2half2_rn(a.z, a.w)};
    *(uint2*)(Ts + (size_t)m * 32 + rq * 4) = *(uint2*)h;
    *(uint2*)(Ts + (size_t)m * 32 + 16 + rq * 4) = make_uint2(0u, 0u);
}

// ---------------------------------------------------------------------------
// fp16 mma GEMM: Y = Xh @ Wh^T + bias + Ts@LBT^T [relu]
// CTA 128x128, BK=32, 256 thr, 4-stage cp.async ring, pitch-80 smem (no swizzle).
// ---------------------------------------------------------------------------
template<bool RELU, bool STORE_HALF, int KTILES, int NT, int GROUP>
__global__ __launch_bounds__(256, 2) void gemm16(
    const __half* __restrict__ Xh, const __half* __restrict__ Wh,
    const float* __restrict__ bias,
    const __half* __restrict__ Tsh, const __half* __restrict__ LBTh,
    float* __restrict__ Yf, __half* __restrict__ Yh)
{
    constexpr int K   = KTILES * 32;
    constexpr int NTILES = NT / 128;
    constexpr int TOT = KTILES + 1;
    constexpr int PITCH = 80;                 // bytes per 32-half row
    constexpr int ASZ = 128 * PITCH;          // 10 KB
    constexpr int STG = 2 * ASZ;              // 20 KB
    constexpr int NST = 4;

    extern __shared__ __align__(16) char smem[];
    float* sbias = (float*)(smem + NST * STG);
    uint32_t sbase;
    asm("{ .reg .u64 t; cvta.to.shared.u64 t, %1; cvt.u32.u64 %0, t; }"
        : "=r"(sbase) : "l"(smem));

    const int tid  = threadIdx.x;
    const int lane = tid & 31;
    const int wid  = tid >> 5;
    const int wm = wid & 3, wn = wid >> 2;    // 4(m) x 2(n)
    const int lr = lane >> 2, lc = lane & 3;

    constexpr int NPG = GROUP * NTILES;
    const int pid = blockIdx.x;
    const int grp = pid / NPG, rem = pid % NPG;
    const int bm0 = (grp * GROUP + rem % GROUP) * 128;
    const int bn0 = (rem / GROUP) * 128;

    if (tid < 128) sbias[tid] = bias[bn0 + tid];

    const int frow = tid >> 1;                // 0..127
    const int fc0  = (tid & 1) * 2;           // chunk 0/2

    auto FILL = [&](int it) {
        if (it < TOT) {
            const uint32_t st = sbase + (uint32_t)(it % NST) * STG;
            const bool mn = (it < KTILES);
            const int k0 = it * 32;
#pragma unroll
            for (int c = fc0; c < fc0 + 2; c++) {
                const __half* ga = mn ? Xh + (size_t)(bm0 + frow) * K + k0 + c * 8
                                      : Tsh + (size_t)(bm0 + frow) * 32 + c * 8;
                const __half* gb = mn ? Wh + (size_t)(bn0 + frow) * K + k0 + c * 8
                                      : LBTh + (size_t)(bn0 + frow) * 32 + c * 8;
                cp16(st + (uint32_t)(frow * PITCH + c * 16), ga);
                cp16(st + (uint32_t)(ASZ + frow * PITCH + c * 16), gb);
            }
        }
        asm volatile("cp.async.commit_group;" ::: "memory");
    };

    float acc[2][8][4];
#pragma unroll
    for (int i = 0; i < 2; i++)
#pragma unroll
        for (int j = 0; j < 8; j++)
#pragma unroll
            for (int k = 0; k < 4; k++) acc[i][j][k] = 0.f;

#pragma unroll
    for (int p = 0; p < NST - 1; ++p) FILL(p);

    // per-lane ldmatrix address components
    const int arow = wm * 32 + (lane & 15);          // + mt*16
    const int asel = lane >> 4;                      // k-chunk select
    const int brow = wn * 64 + ((lane >> 4) << 3) + (lane & 7);   // + np*16
    const int bsel = (lane >> 3) & 1;

    for (int it = 0; it < TOT; ++it) {
        asm volatile("cp.async.wait_group %0;" :: "n"(NST - 2) : "memory");
        __syncthreads();

        const uint32_t sA = sbase + (uint32_t)(it % NST) * STG;
        const uint32_t sB = sA + ASZ;
#pragma unroll
        for (int ks = 0; ks < 2; ks++) {
            uint32_t a[2][4];
#pragma unroll
            for (int mt = 0; mt < 2; mt++)
                ldm4(a[mt], sA + (uint32_t)((arow + mt * 16) * PITCH
                                            + (ks * 2 + asel) * 16));
#pragma unroll
            for (int np = 0; np < 4; np++) {
                uint32_t b[4];
                ldm4(b, sB + (uint32_t)((brow + np * 16) * PITCH
                                        + (ks * 2 + bsel) * 16));
#pragma unroll
                for (int mt = 0; mt < 2; mt++) {
                    mma16816(acc[mt][2 * np],     a[mt], b[0], b[1]);
                    mma16816(acc[mt][2 * np + 1], a[mt], b[2], b[3]);
                }
            }
        }
        FILL(it + NST - 1);
    }

    // epilogue: bias (+relu); store float (out) or half (x2)
#pragma unroll
    for (int mt = 0; mt < 2; mt++) {
        const int m = bm0 + 32 * wm + 16 * mt + lr;
#pragma unroll
        for (int nt = 0; nt < 8; nt++) {
            const int ncol = 64 * wn + 8 * nt + 2 * lc;
            const float b0 = sbias[ncol], b1 = sbias[ncol + 1];
            float v0 = acc[mt][nt][0] + b0, v1 = acc[mt][nt][1] + b1;
            float v2 = acc[mt][nt][2] + b0, v3 = acc[mt][nt][3] + b1;
            if (RELU) {
                v0 = fmaxf(v0, 0.f); v1 = fmaxf(v1, 0.f);
                v2 = fmaxf(v2, 0.f); v3 = fmaxf(v3, 0.f);
            }
            if (STORE_HALF) {
                *(__half2*)(Yh + (size_t)m * NT + bn0 + ncol) =
                    __floats2half2_rn(v0, v1);
                *(__half2*)(Yh + (size_t)(m + 8) * NT + bn0 + ncol) =
                    __floats2half2_rn(v2, v3);
            } else {
                *(float2*)(Yf + (size_t)m * NT + bn0 + ncol)       = make_float2(v0, v1);
                *(float2*)(Yf + (size_t)(m + 8) * NT + bn0 + ncol) = make_float2(v2, v3);
            }
        }
    }
}

// ---------------------------------------------------------------------------
extern "C" void kernel_launch(void* const* d_in, const int* in_sizes, int n_in,
                              void* d_out, int out_size)
{
    const float* x1      = (const float*)d_in[0];
    const int*   w_up_q  = (const int*)  d_in[1];
    const float* w_up_sc = (const float*)d_in[2];
    const float* b_up    = (const float*)d_in[3];
    const float* w_up_la = (const float*)d_in[4];
    const float* w_up_lb = (const float*)d_in[5];
    const int*   w_dn_q  = (const int*)  d_in[6];
    const float* w_dn_sc = (const float*)d_in[7];
    const float* b_dn    = (const float*)d_in[8];
    const float* w_dn_la = (const float*)d_in[9];
    const float* w_dn_lb = (const float*)d_in[10];
    float*       out     = (float*)d_out;

    __half *x1h, *x2h, *wh, *lbt, *tsh;
    float *tp;
    cudaGetSymbolAddress((void**)&x1h, g_x1h);
    cudaGetSymbolAddress((void**)&x2h, g_x2h);
    cudaGetSymbolAddress((void**)&wh,  g_wh);
    cudaGetSymbolAddress((void**)&lbt, g_lbt);
    cudaGetSymbolAddress((void**)&tsh, g_tsh);
    cudaGetSymbolAddress((void**)&tp,  g_tp);

    constexpr int SMEM = 4 * (2 * 128 * 80) + 512;   // 80 KB + bias
    cudaFuncSetAttribute(gemm16<true, true, 64, H_DIM, 16>,
                         cudaFuncAttributeMaxDynamicSharedMemorySize, SMEM);
    cudaFuncSetAttribute(gemm16<false, false, 256, D_DIM, 32>,
                         cudaFuncAttributeMaxDynamicSharedMemorySize, SMEM);

    // ---- layer 1 ----
    cvt_x<<<(M_TOK * D_DIM / 8) / 256, 256>>>(x1, x1h);
    dq_w<<<((size_t)H_DIM * D_DIM / 8) / 256, 256>>>(w_up_q, w_up_sc, wh, D_DIM);
    tr_lb<<<H_DIM / 256, 256>>>(w_up_lb, lbt, H_DIM);
    lora_t<<<dim3(M_TOK / 32, 4), 256>>>(x1h, w_up_la, tp, D_DIM, D_DIM / 4);
    lora_sum<<<128, 256>>>(tp, tsh, 4);
    gemm16<true, true, 64, H_DIM, 16><<<(M_TOK / 128) * (H_DIM / 128), 256, SMEM>>>(
        x1h, wh, b_up, tsh, lbt, nullptr, x2h);

    // ---- layer 2 ----
    dq_w<<<((size_t)D_DIM * H_DIM / 8) / 256, 256>>>(w_dn_q, w_dn_sc, wh, H_DIM);
    tr_lb<<<D_DIM / 256, 256>>>(w_dn_lb, lbt, D_DIM);
    lora_t<<<dim3(M_TOK / 32, 8), 256>>>(x2h, w_dn_la, tp, H_DIM, H_DIM / 8);
    lora_sum<<<128, 256>>>(tp, tsh, 8);
    gemm16<false, false, 256, D_DIM, 32><<<(M_TOK / 128) * (D_DIM / 128), 256, SMEM>>>(
        x2h, wh, b_dn, tsh, lbt, out, nullptr);
}